// round 1
// baseline (speedup 1.0000x reference)
#include <cuda_runtime.h>
#include <math.h>

#define HID 128
#define NG  256

// -------- scratch (static device globals; no allocations allowed) ----------
__device__ float g_agg [50000 * HID];
__device__ float g_buf0[50000 * HID];
__device__ float g_buf1[50000 * HID];
// pool layout: ssum [NG*HID] | smax [NG*HID] | cnt [NG]
__device__ float g_pool[NG * HID * 2 + NG];

// ---------------------------------------------------------------------------
__global__ void zero_kernel(float* __restrict__ p, int n) {
    int i = blockIdx.x * blockDim.x + threadIdx.x;
    int stride = gridDim.x * blockDim.x;
    for (; i < n; i += stride) p[i] = 0.0f;
}

// ---------------------------------------------------------------------------
// Edge scatter: agg[dst] += h[src].  One warp-slice per edge row chunk,
// float4 gather (coalesced within edge), scalar fp32 atomics to L2.
template <int DIM>
__global__ void scatter_kernel(const float* __restrict__ h,
                               const int* __restrict__ src,
                               const int* __restrict__ dst,
                               float* __restrict__ agg, int n_edges) {
    const int C4 = DIM / 4;
    int tid = blockIdx.x * blockDim.x + threadIdx.x;
    int e = tid / C4;
    int c = tid - e * C4;
    if (e >= n_edges) return;
    int s = src[e];
    int d = dst[e];
    float4 v = *reinterpret_cast<const float4*>(h + (size_t)s * DIM + c * 4);
    float* p = agg + (size_t)d * DIM + c * 4;
    atomicAdd(p + 0, v.x);
    atomicAdd(p + 1, v.y);
    atomicAdd(p + 2, v.z);
    atomicAdd(p + 3, v.w);
}

// ---------------------------------------------------------------------------
// Fused GIN MLP: out = relu( relu((hin+agg) @ W1 + b1) @ W2 + b2 )
// CTA: 256 threads, 64-row tile. W1, W2, biases, z-tile, t-tile all in smem.
// Thread micro-tile: 4 rows x 8 cols.
template <int K1>
__global__ void __launch_bounds__(256, 1)
mlp_kernel(const float* __restrict__ hin, const float* __restrict__ agg,
           const float* __restrict__ w1, const float* __restrict__ b1,
           const float* __restrict__ w2, const float* __restrict__ b2,
           float* __restrict__ out, int n_nodes) {
    extern __shared__ float smem[];
    float* sW1 = smem;                       // K1*HID
    float* sW2 = sW1 + K1 * HID;             // HID*HID
    float* sB  = sW2 + HID * HID;            // 2*HID (b1 | b2)
    float* sZ  = sB + 2 * HID;               // 64*(K1+4)
    float* sT  = sZ + 64 * (K1 + 4);         // 64*(HID+4)

    const int t = threadIdx.x;

    // stage weights + biases
    {
        const float4* w1v = reinterpret_cast<const float4*>(w1);
        float4* s1v = reinterpret_cast<float4*>(sW1);
        for (int i = t; i < K1 * HID / 4; i += 256) s1v[i] = w1v[i];
        const float4* w2v = reinterpret_cast<const float4*>(w2);
        float4* s2v = reinterpret_cast<float4*>(sW2);
        for (int i = t; i < HID * HID / 4; i += 256) s2v[i] = w2v[i];
        if (t < HID) { sB[t] = b1[t]; sB[HID + t] = b2[t]; }
    }

    // stage z tile = hin + agg (zero-padded past n_nodes)
    const int row0 = blockIdx.x * 64;
    {
        const int C4 = K1 / 4;
        for (int i = t; i < 64 * C4; i += 256) {
            int r = i / C4, c4 = i - r * C4;
            int gr = row0 + r;
            float4 v = make_float4(0.f, 0.f, 0.f, 0.f);
            if (gr < n_nodes) {
                float4 a = *reinterpret_cast<const float4*>(hin + (size_t)gr * K1 + c4 * 4);
                float4 b = *reinterpret_cast<const float4*>(agg + (size_t)gr * K1 + c4 * 4);
                v = make_float4(a.x + b.x, a.y + b.y, a.z + b.z, a.w + b.w);
            }
            *reinterpret_cast<float4*>(sZ + r * (K1 + 4) + c4 * 4) = v;
        }
    }
    __syncthreads();

    const int tx = t & 15;       // 16 col-groups of 8
    const int ty = t >> 4;       // 16 row-groups of 4

    // ---- matmul 1: t = relu(z @ W1 + b1) ----
    {
        float acc[4][8];
        #pragma unroll
        for (int i = 0; i < 4; i++)
            #pragma unroll
            for (int j = 0; j < 8; j++) acc[i][j] = 0.f;

        #pragma unroll 8
        for (int k = 0; k < K1; k++) {
            float a[4];
            #pragma unroll
            for (int i = 0; i < 4; i++) a[i] = sZ[(ty * 4 + i) * (K1 + 4) + k];
            float4 bA = *reinterpret_cast<const float4*>(sW1 + k * HID + tx * 8);
            float4 bB = *reinterpret_cast<const float4*>(sW1 + k * HID + tx * 8 + 4);
            const float b[8] = {bA.x, bA.y, bA.z, bA.w, bB.x, bB.y, bB.z, bB.w};
            #pragma unroll
            for (int i = 0; i < 4; i++)
                #pragma unroll
                for (int j = 0; j < 8; j++) acc[i][j] += a[i] * b[j];
        }
        #pragma unroll
        for (int i = 0; i < 4; i++) {
            int r = ty * 4 + i;
            int c = tx * 8;
            float4 o0 = make_float4(fmaxf(acc[i][0] + sB[c + 0], 0.f),
                                    fmaxf(acc[i][1] + sB[c + 1], 0.f),
                                    fmaxf(acc[i][2] + sB[c + 2], 0.f),
                                    fmaxf(acc[i][3] + sB[c + 3], 0.f));
            float4 o1 = make_float4(fmaxf(acc[i][4] + sB[c + 4], 0.f),
                                    fmaxf(acc[i][5] + sB[c + 5], 0.f),
                                    fmaxf(acc[i][6] + sB[c + 6], 0.f),
                                    fmaxf(acc[i][7] + sB[c + 7], 0.f));
            *reinterpret_cast<float4*>(sT + r * (HID + 4) + c) = o0;
            *reinterpret_cast<float4*>(sT + r * (HID + 4) + c + 4) = o1;
        }
    }
    __syncthreads();

    // ---- matmul 2: out = relu(t @ W2 + b2) ----
    {
        float acc[4][8];
        #pragma unroll
        for (int i = 0; i < 4; i++)
            #pragma unroll
            for (int j = 0; j < 8; j++) acc[i][j] = 0.f;

        #pragma unroll 8
        for (int k = 0; k < HID; k++) {
            float a[4];
            #pragma unroll
            for (int i = 0; i < 4; i++) a[i] = sT[(ty * 4 + i) * (HID + 4) + k];
            float4 bA = *reinterpret_cast<const float4*>(sW2 + k * HID + tx * 8);
            float4 bB = *reinterpret_cast<const float4*>(sW2 + k * HID + tx * 8 + 4);
            const float b[8] = {bA.x, bA.y, bA.z, bA.w, bB.x, bB.y, bB.z, bB.w};
            #pragma unroll
            for (int i = 0; i < 4; i++)
                #pragma unroll
                for (int j = 0; j < 8; j++) acc[i][j] += a[i] * b[j];
        }
        #pragma unroll
        for (int i = 0; i < 4; i++) {
            int gr = row0 + ty * 4 + i;
            if (gr >= n_nodes) continue;
            int c = tx * 8;
            float4 o0 = make_float4(fmaxf(acc[i][0] + sB[HID + c + 0], 0.f),
                                    fmaxf(acc[i][1] + sB[HID + c + 1], 0.f),
                                    fmaxf(acc[i][2] + sB[HID + c + 2], 0.f),
                                    fmaxf(acc[i][3] + sB[HID + c + 3], 0.f));
            float4 o1 = make_float4(fmaxf(acc[i][4] + sB[HID + c + 4], 0.f),
                                    fmaxf(acc[i][5] + sB[HID + c + 5], 0.f),
                                    fmaxf(acc[i][6] + sB[HID + c + 6], 0.f),
                                    fmaxf(acc[i][7] + sB[HID + c + 7], 0.f));
            *reinterpret_cast<float4*>(out + (size_t)gr * HID + c) = o0;
            *reinterpret_cast<float4*>(out + (size_t)gr * HID + c + 4) = o1;
        }
    }
}

// ---------------------------------------------------------------------------
// Readout: batch_idx is sorted, so run-length accumulate in registers and
// flush one atomic per (graph, column) run boundary. h >= 0 (post-ReLU), so
// atomicMax on int-punned floats with 0-init is exact and matches the
// reference's where(cnt>0, segmax, 0).
__global__ void readout_kernel(const float* __restrict__ h,
                               const int* __restrict__ batch, int n_nodes,
                               float* __restrict__ ssum, float* __restrict__ smax,
                               float* __restrict__ cnt) {
    int c = threadIdx.x;          // 128 threads = one column each
    int n0 = blockIdx.x * 128;
    if (n0 >= n_nodes) return;
    int nend = min(n0 + 128, n_nodes);
    int curg = batch[n0];
    float rs = 0.f, rm = 0.f, rc = 0.f;
    for (int n = n0; n < nend; n++) {
        int g = __ldg(batch + n);
        if (g != curg) {
            atomicAdd(&ssum[curg * HID + c], rs);
            atomicMax(reinterpret_cast<int*>(&smax[curg * HID + c]), __float_as_int(rm));
            if (c == 0) atomicAdd(&cnt[curg], rc);
            rs = 0.f; rm = 0.f; rc = 0.f; curg = g;
        }
        float v = h[(size_t)n * HID + c];
        rs += v;
        rm = fmaxf(rm, v);
        rc += 1.f;
    }
    atomicAdd(&ssum[curg * HID + c], rs);
    atomicMax(reinterpret_cast<int*>(&smax[curg * HID + c]), __float_as_int(rm));
    if (c == 0) atomicAdd(&cnt[curg], rc);
}

// ---------------------------------------------------------------------------
// Head: one block per graph. repr = [mean | max] (256), hh = relu(repr@W1+b1),
// logit = hh@w2 + b2, out = sigmoid(logit).
__global__ void head_kernel(const float* __restrict__ pool,
                            const float* __restrict__ w1, const float* __restrict__ b1,
                            const float* __restrict__ w2, const float* __restrict__ b2,
                            float* __restrict__ out) {
    __shared__ float repr[2 * HID];
    __shared__ float red[4];
    int g = blockIdx.x;
    int n = threadIdx.x;  // 128
    const float* ssum = pool;
    const float* smax = pool + NG * HID;
    const float* cnt  = pool + 2 * NG * HID;

    float cg = cnt[g];
    float dv = fmaxf(cg, 1.f);
    repr[n]       = ssum[g * HID + n] / dv;
    repr[HID + n] = (cg > 0.f) ? smax[g * HID + n] : 0.f;
    __syncthreads();

    float acc = b1[n];
    #pragma unroll 8
    for (int k = 0; k < 2 * HID; k++) acc += repr[k] * w1[k * HID + n];
    float p = fmaxf(acc, 0.f) * w2[n];

    #pragma unroll
    for (int off = 16; off > 0; off >>= 1) p += __shfl_down_sync(0xffffffffu, p, off);
    if ((n & 31) == 0) red[n >> 5] = p;
    __syncthreads();
    if (n == 0) {
        float logit = red[0] + red[1] + red[2] + red[3] + b2[0];
        out[g] = 1.f / (1.f + expf(-logit));
    }
}

// ---------------------------------------------------------------------------
extern "C" void kernel_launch(void* const* d_in, const int* in_sizes, int n_in,
                              void* d_out, int out_size) {
    const float* x      = (const float*)d_in[0];
    const int*   ei     = (const int*)  d_in[1];
    const int*   batch  = (const int*)  d_in[2];
    const float* g0w1 = (const float*)d_in[3],  *g0b1 = (const float*)d_in[4];
    const float* g0w2 = (const float*)d_in[5],  *g0b2 = (const float*)d_in[6];
    const float* g1w1 = (const float*)d_in[7],  *g1b1 = (const float*)d_in[8];
    const float* g1w2 = (const float*)d_in[9],  *g1b2 = (const float*)d_in[10];
    const float* g2w1 = (const float*)d_in[11], *g2b1 = (const float*)d_in[12];
    const float* g2w2 = (const float*)d_in[13], *g2b2 = (const float*)d_in[14];
    const float* hw1  = (const float*)d_in[15], *hb1  = (const float*)d_in[16];
    const float* hw2  = (const float*)d_in[17], *hb2  = (const float*)d_in[18];
    float* out = (float*)d_out;

    const int N = in_sizes[2];          // 50000 nodes
    const int E = in_sizes[1] / 2;      // 800000 edges
    const int IN_DIM = in_sizes[0] / N; // 64
    const int* src = ei;
    const int* dst = ei + E;

    float *agg, *buf0, *buf1, *pool;
    cudaGetSymbolAddress((void**)&agg,  g_agg);
    cudaGetSymbolAddress((void**)&buf0, g_buf0);
    cudaGetSymbolAddress((void**)&buf1, g_buf1);
    cudaGetSymbolAddress((void**)&pool, g_pool);

    const int SM64  = (IN_DIM * HID + HID * HID + 2 * HID + 64 * (IN_DIM + 4) + 64 * (HID + 4)) * 4;
    const int SM128 = (HID * HID * 2 + 2 * HID + 64 * (HID + 4) * 2) * 4;
    cudaFuncSetAttribute(mlp_kernel<64>,  cudaFuncAttributeMaxDynamicSharedMemorySize, SM64);
    cudaFuncSetAttribute(mlp_kernel<128>, cudaFuncAttributeMaxDynamicSharedMemorySize, SM128);

    const int mlp_blocks = (N + 63) / 64;

    // ---- layer 0 (in dim 64) ----
    zero_kernel<<<2048, 256>>>(agg, N * IN_DIM);
    scatter_kernel<64><<<(E * 16 + 255) / 256, 256>>>(x, src, dst, agg, E);
    mlp_kernel<64><<<mlp_blocks, 256, SM64>>>(x, agg, g0w1, g0b1, g0w2, g0b2, buf0, N);

    // ---- layer 1 ----
    zero_kernel<<<2048, 256>>>(agg, N * HID);
    scatter_kernel<128><<<(E * 32 + 255) / 256, 256>>>(buf0, src, dst, agg, E);
    mlp_kernel<128><<<mlp_blocks, 256, SM128>>>(buf0, agg, g1w1, g1b1, g1w2, g1b2, buf1, N);

    // ---- layer 2 ----
    zero_kernel<<<2048, 256>>>(agg, N * HID);
    scatter_kernel<128><<<(E * 32 + 255) / 256, 256>>>(buf1, src, dst, agg, E);
    mlp_kernel<128><<<mlp_blocks, 256, SM128>>>(buf1, agg, g2w1, g2b1, g2w2, g2b2, buf0, N);

    // ---- readout + head ----
    zero_kernel<<<256, 256>>>(pool, NG * HID * 2 + NG);
    readout_kernel<<<(N + 127) / 128, 128>>>(buf0, batch, N,
                                             pool, pool + NG * HID, pool + 2 * NG * HID);
    head_kernel<<<NG, 128>>>(pool, hw1, hb1, hw2, hb2, out);
}

// round 4
// speedup vs baseline: 1.6285x; 1.6285x over previous
#include <cuda_runtime.h>
#include <math.h>

#define HID 128
#define NG  256
#define MAXN 50000
#define MAXE 800000

// -------- scratch (static device globals; no allocations allowed) ----------
__device__ float g_agg [MAXN * HID];
__device__ float g_buf0[MAXN * HID];
__device__ float g_buf1[MAXN * HID];
__device__ int   g_deg [MAXN + 1];
__device__ int   g_off [MAXN + 1];
__device__ int   g_cur [MAXN];
__device__ int   g_eidx[MAXE];
// pool layout: ssum [NG*HID] | smax [NG*HID] | cnt [NG]
__device__ float g_pool[NG * HID * 2 + NG];

// ---------------------------------------------------------------------------
__global__ void zero_f(float* __restrict__ p, int n) {
    int i = blockIdx.x * blockDim.x + threadIdx.x;
    int s = gridDim.x * blockDim.x;
    for (; i < n; i += s) p[i] = 0.0f;
}
__global__ void zero_i(int* __restrict__ p, int n) {
    int i = blockIdx.x * blockDim.x + threadIdx.x;
    int s = gridDim.x * blockDim.x;
    for (; i < n; i += s) p[i] = 0;
}

// ---------------- CSR build ------------------------------------------------
__global__ void hist_kernel(const int* __restrict__ dst, int* __restrict__ deg, int E) {
    int i = blockIdx.x * blockDim.x + threadIdx.x;
    if (i < E) atomicAdd(&deg[dst[i]], 1);
}

// single-block exclusive scan over n<=50000 elements (chunked, 1024 threads)
__global__ void scan_kernel(const int* __restrict__ deg, int* __restrict__ off,
                            int* __restrict__ cur, int n) {
    __shared__ int wsum[32];
    __shared__ int s_run;
    int t = threadIdx.x;
    int lane = t & 31, wid = t >> 5;
    if (t == 0) s_run = 0;
    __syncthreads();
    for (int base = 0; base < n; base += 1024) {
        int i = base + t;
        int v = (i < n) ? deg[i] : 0;
        int x = v;
        #pragma unroll
        for (int o = 1; o < 32; o <<= 1) {
            int y = __shfl_up_sync(~0u, x, o);
            if (lane >= o) x += y;
        }
        if (lane == 31) wsum[wid] = x;
        __syncthreads();
        if (t < 32) {
            int w = wsum[t];
            #pragma unroll
            for (int o = 1; o < 32; o <<= 1) {
                int y = __shfl_up_sync(~0u, w, o);
                if (t >= o) w += y;
            }
            wsum[t] = w;
        }
        __syncthreads();
        int woff = (wid > 0) ? wsum[wid - 1] : 0;
        int excl = s_run + woff + x - v;
        if (i < n) { off[i] = excl; cur[i] = excl; }
        __syncthreads();
        if (t == 0) s_run += wsum[31];
        __syncthreads();
    }
    if (t == 0) off[n] = s_run;
}

__global__ void fill_kernel(const int* __restrict__ src, const int* __restrict__ dst,
                            int* __restrict__ cur, int* __restrict__ eidx, int E) {
    int i = blockIdx.x * blockDim.x + threadIdx.x;
    if (i < E) {
        int p = atomicAdd(&cur[dst[i]], 1);
        eidx[p] = src[i];
    }
}

// ---------------- gather aggregation: z[i] = h[i] + sum_{j->i} h[j] --------
// one warp per node, each lane owns a float4 column slice; edges unrolled x4.
template <int DIM>
__global__ void gather_kernel(const float* __restrict__ h,
                              const int* __restrict__ off,
                              const int* __restrict__ eidx,
                              float* __restrict__ z, int n_nodes) {
    const int C4 = DIM / 4;
    int warp = (blockIdx.x * blockDim.x + threadIdx.x) >> 5;
    int lane = threadIdx.x & 31;
    if (warp >= n_nodes || lane >= C4) return;
    const float* hp = h + (size_t)lane * 4;
    int a = off[warp], b = off[warp + 1];
    // init with the node's own row (GIN self term)
    float4 acc = *reinterpret_cast<const float4*>(hp + (size_t)warp * DIM);
    int j = a;
    for (; j + 4 <= b; j += 4) {
        int s0 = __ldg(eidx + j);
        int s1 = __ldg(eidx + j + 1);
        int s2 = __ldg(eidx + j + 2);
        int s3 = __ldg(eidx + j + 3);
        float4 v0 = *reinterpret_cast<const float4*>(hp + (size_t)s0 * DIM);
        float4 v1 = *reinterpret_cast<const float4*>(hp + (size_t)s1 * DIM);
        float4 v2 = *reinterpret_cast<const float4*>(hp + (size_t)s2 * DIM);
        float4 v3 = *reinterpret_cast<const float4*>(hp + (size_t)s3 * DIM);
        acc.x += v0.x + v1.x + v2.x + v3.x;
        acc.y += v0.y + v1.y + v2.y + v3.y;
        acc.z += v0.z + v1.z + v2.z + v3.z;
        acc.w += v0.w + v1.w + v2.w + v3.w;
    }
    for (; j < b; j++) {
        int s = __ldg(eidx + j);
        float4 v = *reinterpret_cast<const float4*>(hp + (size_t)s * DIM);
        acc.x += v.x; acc.y += v.y; acc.z += v.z; acc.w += v.w;
    }
    *reinterpret_cast<float4*>(z + (size_t)warp * DIM + lane * 4) = acc;
}

// ---------------------------------------------------------------------------
// Fused GIN MLP: out = relu( relu(z @ W1 + b1) @ W2 + b2 )
// CTA: 256 threads, 64-row tile. Thread micro-tile: 4 rows x 8 cols.
template <int K1>
__global__ void __launch_bounds__(256, 1)
mlp_kernel(const float* __restrict__ z,
           const float* __restrict__ w1, const float* __restrict__ b1,
           const float* __restrict__ w2, const float* __restrict__ b2,
           float* __restrict__ out, int n_nodes) {
    extern __shared__ float smem[];
    float* sW1 = smem;                       // K1*HID
    float* sW2 = sW1 + K1 * HID;             // HID*HID
    float* sB  = sW2 + HID * HID;            // 2*HID (b1 | b2)
    float* sZ  = sB + 2 * HID;               // 64*(K1+4)
    float* sT  = sZ + 64 * (K1 + 4);         // 64*(HID+4)

    const int t = threadIdx.x;

    // stage weights + biases
    {
        const float4* w1v = reinterpret_cast<const float4*>(w1);
        float4* s1v = reinterpret_cast<float4*>(sW1);
        for (int i = t; i < K1 * HID / 4; i += 256) s1v[i] = w1v[i];
        const float4* w2v = reinterpret_cast<const float4*>(w2);
        float4* s2v = reinterpret_cast<float4*>(sW2);
        for (int i = t; i < HID * HID / 4; i += 256) s2v[i] = w2v[i];
        if (t < HID) { sB[t] = b1[t]; sB[HID + t] = b2[t]; }
    }

    // stage z tile (zero-padded past n_nodes)
    const int row0 = blockIdx.x * 64;
    {
        const int C4 = K1 / 4;
        for (int i = t; i < 64 * C4; i += 256) {
            int r = i / C4, c4 = i - r * C4;
            int gr = row0 + r;
            float4 v = make_float4(0.f, 0.f, 0.f, 0.f);
            if (gr < n_nodes)
                v = *reinterpret_cast<const float4*>(z + (size_t)gr * K1 + c4 * 4);
            *reinterpret_cast<float4*>(sZ + r * (K1 + 4) + c4 * 4) = v;
        }
    }
    __syncthreads();

    const int tx = t & 15;       // 16 col-groups of 8
    const int ty = t >> 4;       // 16 row-groups of 4

    // ---- matmul 1: t = relu(z @ W1 + b1) ----
    {
        float acc[4][8];
        #pragma unroll
        for (int i = 0; i < 4; i++)
            #pragma unroll
            for (int j = 0; j < 8; j++) acc[i][j] = 0.f;

        #pragma unroll 8
        for (int k = 0; k < K1; k++) {
            float a[4];
            #pragma unroll
            for (int i = 0; i < 4; i++) a[i] = sZ[(ty * 4 + i) * (K1 + 4) + k];
            float4 bA = *reinterpret_cast<const float4*>(sW1 + k * HID + tx * 8);
            float4 bB = *reinterpret_cast<const float4*>(sW1 + k * HID + tx * 8 + 4);
            const float b[8] = {bA.x, bA.y, bA.z, bA.w, bB.x, bB.y, bB.z, bB.w};
            #pragma unroll
            for (int i = 0; i < 4; i++)
                #pragma unroll
                for (int j = 0; j < 8; j++) acc[i][j] += a[i] * b[j];
        }
        #pragma unroll
        for (int i = 0; i < 4; i++) {
            int r = ty * 4 + i;
            int c = tx * 8;
            float4 o0 = make_float4(fmaxf(acc[i][0] + sB[c + 0], 0.f),
                                    fmaxf(acc[i][1] + sB[c + 1], 0.f),
                                    fmaxf(acc[i][2] + sB[c + 2], 0.f),
                                    fmaxf(acc[i][3] + sB[c + 3], 0.f));
            float4 o1 = make_float4(fmaxf(acc[i][4] + sB[c + 4], 0.f),
                                    fmaxf(acc[i][5] + sB[c + 5], 0.f),
                                    fmaxf(acc[i][6] + sB[c + 6], 0.f),
                                    fmaxf(acc[i][7] + sB[c + 7], 0.f));
            *reinterpret_cast<float4*>(sT + r * (HID + 4) + c) = o0;
            *reinterpret_cast<float4*>(sT + r * (HID + 4) + c + 4) = o1;
        }
    }
    __syncthreads();

    // ---- matmul 2: out = relu(t @ W2 + b2) ----
    {
        float acc[4][8];
        #pragma unroll
        for (int i = 0; i < 4; i++)
            #pragma unroll
            for (int j = 0; j < 8; j++) acc[i][j] = 0.f;

        #pragma unroll 8
        for (int k = 0; k < HID; k++) {
            float a[4];
            #pragma unroll
            for (int i = 0; i < 4; i++) a[i] = sT[(ty * 4 + i) * (HID + 4) + k];
            float4 bA = *reinterpret_cast<const float4*>(sW2 + k * HID + tx * 8);
            float4 bB = *reinterpret_cast<const float4*>(sW2 + k * HID + tx * 8 + 4);
            const float b[8] = {bA.x, bA.y, bA.z, bA.w, bB.x, bB.y, bB.z, bB.w};
            #pragma unroll
            for (int i = 0; i < 4; i++)
                #pragma unroll
                for (int j = 0; j < 8; j++) acc[i][j] += a[i] * b[j];
        }
        #pragma unroll
        for (int i = 0; i < 4; i++) {
            int gr = row0 + ty * 4 + i;
            if (gr >= n_nodes) continue;
            int c = tx * 8;
            float4 o0 = make_float4(fmaxf(acc[i][0] + sB[HID + c + 0], 0.f),
                                    fmaxf(acc[i][1] + sB[HID + c + 1], 0.f),
                                    fmaxf(acc[i][2] + sB[HID + c + 2], 0.f),
                                    fmaxf(acc[i][3] + sB[HID + c + 3], 0.f));
            float4 o1 = make_float4(fmaxf(acc[i][4] + sB[HID + c + 4], 0.f),
                                    fmaxf(acc[i][5] + sB[HID + c + 5], 0.f),
                                    fmaxf(acc[i][6] + sB[HID + c + 6], 0.f),
                                    fmaxf(acc[i][7] + sB[HID + c + 7], 0.f));
            *reinterpret_cast<float4*>(out + (size_t)gr * HID + c) = o0;
            *reinterpret_cast<float4*>(out + (size_t)gr * HID + c + 4) = o1;
        }
    }
}

// ---------------------------------------------------------------------------
// Readout: batch_idx sorted -> run-length accumulate, flush atomics per run.
// h >= 0 post-ReLU, so int-punned atomicMax with 0-init is exact and matches
// where(cnt>0, segmax, 0).
__global__ void readout_kernel(const float* __restrict__ h,
                               const int* __restrict__ batch, int n_nodes,
                               float* __restrict__ ssum, float* __restrict__ smax,
                               float* __restrict__ cnt) {
    int c = threadIdx.x;          // 128 threads = one column each
    int n0 = blockIdx.x * 128;
    if (n0 >= n_nodes) return;
    int nend = min(n0 + 128, n_nodes);
    int curg = batch[n0];
    float rs = 0.f, rm = 0.f, rc = 0.f;
    for (int n = n0; n < nend; n++) {
        int g = __ldg(batch + n);
        if (g != curg) {
            atomicAdd(&ssum[curg * HID + c], rs);
            atomicMax(reinterpret_cast<int*>(&smax[curg * HID + c]), __float_as_int(rm));
            if (c == 0) atomicAdd(&cnt[curg], rc);
            rs = 0.f; rm = 0.f; rc = 0.f; curg = g;
        }
        float v = h[(size_t)n * HID + c];
        rs += v;
        rm = fmaxf(rm, v);
        rc += 1.f;
    }
    atomicAdd(&ssum[curg * HID + c], rs);
    atomicMax(reinterpret_cast<int*>(&smax[curg * HID + c]), __float_as_int(rm));
    if (c == 0) atomicAdd(&cnt[curg], rc);
}

// ---------------------------------------------------------------------------
__global__ void head_kernel(const float* __restrict__ pool,
                            const float* __restrict__ w1, const float* __restrict__ b1,
                            const float* __restrict__ w2, const float* __restrict__ b2,
                            float* __restrict__ out) {
    __shared__ float repr[2 * HID];
    __shared__ float red[4];
    int g = blockIdx.x;
    int n = threadIdx.x;  // 128
    const float* ssum = pool;
    const float* smax = pool + NG * HID;
    const float* cnt  = pool + 2 * NG * HID;

    float cg = cnt[g];
    float dv = fmaxf(cg, 1.f);
    repr[n]       = ssum[g * HID + n] / dv;
    repr[HID + n] = (cg > 0.f) ? smax[g * HID + n] : 0.f;
    __syncthreads();

    float acc = b1[n];
    #pragma unroll 8
    for (int k = 0; k < 2 * HID; k++) acc += repr[k] * w1[k * HID + n];
    float p = fmaxf(acc, 0.f) * w2[n];

    #pragma unroll
    for (int off = 16; off > 0; off >>= 1) p += __shfl_down_sync(0xffffffffu, p, off);
    if ((n & 31) == 0) red[n >> 5] = p;
    __syncthreads();
    if (n == 0) {
        float logit = red[0] + red[1] + red[2] + red[3] + b2[0];
        out[g] = 1.f / (1.f + expf(-logit));
    }
}

// ---------------------------------------------------------------------------
extern "C" void kernel_launch(void* const* d_in, const int* in_sizes, int n_in,
                              void* d_out, int out_size) {
    const float* x      = (const float*)d_in[0];
    const int*   ei     = (const int*)  d_in[1];
    const int*   batch  = (const int*)  d_in[2];
    const float* g0w1 = (const float*)d_in[3],  *g0b1 = (const float*)d_in[4];
    const float* g0w2 = (const float*)d_in[5],  *g0b2 = (const float*)d_in[6];
    const float* g1w1 = (const float*)d_in[7],  *g1b1 = (const float*)d_in[8];
    const float* g1w2 = (const float*)d_in[9],  *g1b2 = (const float*)d_in[10];
    const float* g2w1 = (const float*)d_in[11], *g2b1 = (const float*)d_in[12];
    const float* g2w2 = (const float*)d_in[13], *g2b2 = (const float*)d_in[14];
    const float* hw1  = (const float*)d_in[15], *hb1  = (const float*)d_in[16];
    const float* hw2  = (const float*)d_in[17], *hb2  = (const float*)d_in[18];
    float* out = (float*)d_out;

    const int N = in_sizes[2];          // 50000 nodes
    const int E = in_sizes[1] / 2;      // 800000 edges
    const int IN_DIM = in_sizes[0] / N; // 64
    const int* src = ei;
    const int* dst = ei + E;

    float *agg, *buf0, *buf1, *pool;
    int *deg, *off, *cur, *eidx;
    cudaGetSymbolAddress((void**)&agg,  g_agg);
    cudaGetSymbolAddress((void**)&buf0, g_buf0);
    cudaGetSymbolAddress((void**)&buf1, g_buf1);
    cudaGetSymbolAddress((void**)&pool, g_pool);
    cudaGetSymbolAddress((void**)&deg,  g_deg);
    cudaGetSymbolAddress((void**)&off,  g_off);
    cudaGetSymbolAddress((void**)&cur,  g_cur);
    cudaGetSymbolAddress((void**)&eidx, g_eidx);

    const int SM64  = (IN_DIM * HID + HID * HID + 2 * HID + 64 * (IN_DIM + 4) + 64 * (HID + 4)) * 4;
    const int SM128 = (HID * HID * 2 + 2 * HID + 64 * (HID + 4) * 2) * 4;
    cudaFuncSetAttribute(mlp_kernel<64>,  cudaFuncAttributeMaxDynamicSharedMemorySize, SM64);
    cudaFuncSetAttribute(mlp_kernel<128>, cudaFuncAttributeMaxDynamicSharedMemorySize, SM128);

    const int mlp_blocks = (N + 63) / 64;
    const int e_blocks = (E + 255) / 256;
    const int g_blocks = (N + 7) / 8;       // 8 warps/block

    // ---- CSR build (over dst) ----
    zero_i<<<64, 256>>>(deg, N);
    hist_kernel<<<e_blocks, 256>>>(dst, deg, E);
    scan_kernel<<<1, 1024>>>(deg, off, cur, N);
    fill_kernel<<<e_blocks, 256>>>(src, dst, cur, eidx, E);

    // ---- layer 0 (in dim 64) ----
    gather_kernel<64><<<g_blocks, 256>>>(x, off, eidx, agg, N);
    mlp_kernel<64><<<mlp_blocks, 256, SM64>>>(agg, g0w1, g0b1, g0w2, g0b2, buf0, N);

    // ---- layer 1 ----
    gather_kernel<128><<<g_blocks, 256>>>(buf0, off, eidx, agg, N);
    mlp_kernel<128><<<mlp_blocks, 256, SM128>>>(agg, g1w1, g1b1, g1w2, g1b2, buf1, N);

    // ---- layer 2 ----
    gather_kernel<128><<<g_blocks, 256>>>(buf1, off, eidx, agg, N);
    mlp_kernel<128><<<mlp_blocks, 256, SM128>>>(agg, g2w1, g2b1, g2w2, g2b2, buf0, N);

    // ---- readout + head ----
    zero_f<<<256, 256>>>(pool, NG * HID * 2 + NG);
    readout_kernel<<<(N + 127) / 128, 128>>>(buf0, batch, N,
                                             pool, pool + NG * HID, pool + 2 * NG * HID);
    head_kernel<<<NG, 128>>>(pool, hw1, hb1, hw2, hb2, out);
}

// round 16
// speedup vs baseline: 2.4888x; 1.5282x over previous
#include <cuda_runtime.h>
#include <cuda_bf16.h>
#include <mma.h>
#include <math.h>
#include <stdint.h>

using namespace nvcuda;

#define HID 128
#define NG  256
#define MAXN 50000
#define MAXE 800000

// -------- scratch (static device globals; no allocations allowed) ----------
__device__ float g_agg [MAXN * HID];
__device__ float g_buf0[MAXN * HID];
__device__ float g_buf1[MAXN * HID];
__device__ int   g_deg [MAXN + 1];
__device__ int   g_off [MAXN + 1];
__device__ int   g_cur [MAXN];
__device__ int   g_eidx[MAXE];
// pool layout: ssum [NG*HID] | smax [NG*HID] | cnt [NG]
__device__ float g_pool[NG * HID * 2 + NG];

// ---------------------------------------------------------------------------
__global__ void zero_f(float* __restrict__ p, int n) {
    int i = blockIdx.x * blockDim.x + threadIdx.x;
    int s = gridDim.x * blockDim.x;
    for (; i < n; i += s) p[i] = 0.0f;
}
__global__ void zero_i(int* __restrict__ p, int n) {
    int i = blockIdx.x * blockDim.x + threadIdx.x;
    int s = gridDim.x * blockDim.x;
    for (; i < n; i += s) p[i] = 0;
}

// ---------------- CSR build ------------------------------------------------
__global__ void hist_kernel(const int* __restrict__ dst, int* __restrict__ deg, int E) {
    int i = blockIdx.x * blockDim.x + threadIdx.x;
    if (i < E) atomicAdd(&deg[dst[i]], 1);
}

__global__ void scan_kernel(const int* __restrict__ deg, int* __restrict__ off,
                            int* __restrict__ cur, int n) {
    __shared__ int wsum[32];
    __shared__ int s_run;
    int t = threadIdx.x;
    int lane = t & 31, wid = t >> 5;
    if (t == 0) s_run = 0;
    __syncthreads();
    for (int base = 0; base < n; base += 1024) {
        int i = base + t;
        int v = (i < n) ? deg[i] : 0;
        int x = v;
        #pragma unroll
        for (int o = 1; o < 32; o <<= 1) {
            int y = __shfl_up_sync(~0u, x, o);
            if (lane >= o) x += y;
        }
        if (lane == 31) wsum[wid] = x;
        __syncthreads();
        if (t < 32) {
            int w = wsum[t];
            #pragma unroll
            for (int o = 1; o < 32; o <<= 1) {
                int y = __shfl_up_sync(~0u, w, o);
                if (t >= o) w += y;
            }
            wsum[t] = w;
        }
        __syncthreads();
        int woff = (wid > 0) ? wsum[wid - 1] : 0;
        int excl = s_run + woff + x - v;
        if (i < n) { off[i] = excl; cur[i] = excl; }
        __syncthreads();
        if (t == 0) s_run += wsum[31];
        __syncthreads();
    }
    if (t == 0) off[n] = s_run;
}

__global__ void fill_kernel(const int* __restrict__ src, const int* __restrict__ dst,
                            int* __restrict__ cur, int* __restrict__ eidx, int E) {
    int i = blockIdx.x * blockDim.x + threadIdx.x;
    if (i < E) {
        int p = atomicAdd(&cur[dst[i]], 1);
        eidx[p] = src[i];
    }
}

// ---------------- gather aggregation: z[i] = h[i] + sum_{j->i} h[j] --------
template <int DIM>
__global__ void gather_kernel(const float* __restrict__ h,
                              const int* __restrict__ off,
                              const int* __restrict__ eidx,
                              float* __restrict__ z, int n_nodes) {
    const int C4 = DIM / 4;
    int warp = (blockIdx.x * blockDim.x + threadIdx.x) >> 5;
    int lane = threadIdx.x & 31;
    if (warp >= n_nodes || lane >= C4) return;
    const float* hp = h + (size_t)lane * 4;
    int a = off[warp], b = off[warp + 1];
    float4 acc = *reinterpret_cast<const float4*>(hp + (size_t)warp * DIM);
    int j = a;
    for (; j + 4 <= b; j += 4) {
        int s0 = __ldg(eidx + j);
        int s1 = __ldg(eidx + j + 1);
        int s2 = __ldg(eidx + j + 2);
        int s3 = __ldg(eidx + j + 3);
        float4 v0 = *reinterpret_cast<const float4*>(hp + (size_t)s0 * DIM);
        float4 v1 = *reinterpret_cast<const float4*>(hp + (size_t)s1 * DIM);
        float4 v2 = *reinterpret_cast<const float4*>(hp + (size_t)s2 * DIM);
        float4 v3 = *reinterpret_cast<const float4*>(hp + (size_t)s3 * DIM);
        acc.x += v0.x + v1.x + v2.x + v3.x;
        acc.y += v0.y + v1.y + v2.y + v3.y;
        acc.z += v0.z + v1.z + v2.z + v3.z;
        acc.w += v0.w + v1.w + v2.w + v3.w;
    }
    for (; j < b; j++) {
        int s = __ldg(eidx + j);
        float4 v = *reinterpret_cast<const float4*>(hp + (size_t)s * DIM);
        acc.x += v.x; acc.y += v.y; acc.z += v.z; acc.w += v.w;
    }
    *reinterpret_cast<float4*>(z + (size_t)warp * DIM + lane * 4) = acc;
}

// ===================== WMMA bf16 MLP (no inline asm) ========================
// Split-bf16: x = hi + lo; products hh + hl + lh accumulated in fp32.
// SMEM: Ah/Al (tile 128 x 136 bf16), Bh/Bl (W^T 128 x 136 bf16).
// Epilogue scratch (128 x 132 f32) overlays the Bh/Bl region.
static constexpr int AS = 136;                       // bf16 row stride
static constexpr int TILE_B = 128 * AS * 2;          // 34816 bytes
static constexpr int LDS = 132;                      // f32 scratch stride
static constexpr int MMA_SMEM = 1024 + 4 * TILE_B;   // 140288

__device__ __forceinline__ void bf16_split(float x, unsigned short& h, unsigned short& l) {
    __nv_bfloat16 hb = __float2bfloat16(x);
    float hf = __bfloat162float(hb);
    __nv_bfloat16 lb = __float2bfloat16(x - hf);
    h = *reinterpret_cast<unsigned short*>(&hb);
    l = *reinterpret_cast<unsigned short*>(&lb);
}
__device__ __forceinline__ void sst2(char* H, char* L, int eoff, float x0, float x1) {
    unsigned short h0, l0, h1, l1;
    bf16_split(x0, h0, l0);
    bf16_split(x1, h1, l1);
    *reinterpret_cast<uint32_t*>(H + eoff * 2) = ((uint32_t)h1 << 16) | h0;
    *reinterpret_cast<uint32_t*>(L + eoff * 2) = ((uint32_t)l1 << 16) | l0;
}
__device__ __forceinline__ void sst1(char* H, char* L, int eoff, float x) {
    unsigned short h, l;
    bf16_split(x, h, l);
    *reinterpret_cast<unsigned short*>(H + eoff * 2) = h;
    *reinterpret_cast<unsigned short*>(L + eoff * 2) = l;
}

typedef wmma::fragment<wmma::matrix_a, 16, 16, 16, __nv_bfloat16, wmma::row_major> FragA;
typedef wmma::fragment<wmma::matrix_b, 16, 16, 16, __nv_bfloat16, wmma::col_major> FragB;
typedef wmma::fragment<wmma::accumulator, 16, 16, 16, float> FragC;

// Warp GEMM: 64x32 warp tile (4x2 fragments), K = NS*16.
template <int NS>
__device__ void wmma_gemm(FragC acc[4][2],
                          const __nv_bfloat16* Ah, const __nv_bfloat16* Al,
                          const __nv_bfloat16* Bh, const __nv_bfloat16* Bl,
                          int m0, int n0) {
    for (int ks = 0; ks < NS; ks++) {
        const int k0 = ks * 16;
        FragB bh[2], bl[2];
        #pragma unroll
        for (int nt = 0; nt < 2; nt++) {
            wmma::load_matrix_sync(bh[nt], Bh + (n0 + nt * 16) * AS + k0, AS);
            wmma::load_matrix_sync(bl[nt], Bl + (n0 + nt * 16) * AS + k0, AS);
        }
        #pragma unroll
        for (int mt = 0; mt < 4; mt++) {
            FragA ah, al;
            wmma::load_matrix_sync(ah, Ah + (m0 + mt * 16) * AS + k0, AS);
            wmma::load_matrix_sync(al, Al + (m0 + mt * 16) * AS + k0, AS);
            #pragma unroll
            for (int nt = 0; nt < 2; nt++) {
                wmma::mma_sync(acc[mt][nt], ah, bh[nt], acc[mt][nt]);
                wmma::mma_sync(acc[mt][nt], ah, bl[nt], acc[mt][nt]);
                wmma::mma_sync(acc[mt][nt], al, bh[nt], acc[mt][nt]);
            }
        }
    }
}

// Fused GIN MLP: out = relu( relu(z @ W1 + b1) @ W2 + b2 ); 1 CTA / 128 nodes.
template <int K1>
__global__ void __launch_bounds__(256, 1)
mma_mlp(const float* __restrict__ z,
        const float* __restrict__ w1, const float* __restrict__ b1,
        const float* __restrict__ w2, const float* __restrict__ b2,
        float* __restrict__ out, int n_nodes) {
    extern __shared__ char smem[];
    float* sB1 = reinterpret_cast<float*>(smem);
    float* sB2 = sB1 + 128;
    char* Ah = smem + 1024;
    char* Al = Ah + TILE_B;
    char* Bh = Al + TILE_B;
    char* Bl = Bh + TILE_B;
    float* scr = reinterpret_cast<float*>(Bh);   // 128*132*4 = 67584 <= 69632

    const __nv_bfloat16* fAh = reinterpret_cast<const __nv_bfloat16*>(Ah);
    const __nv_bfloat16* fAl = reinterpret_cast<const __nv_bfloat16*>(Al);
    const __nv_bfloat16* fBh = reinterpret_cast<const __nv_bfloat16*>(Bh);
    const __nv_bfloat16* fBl = reinterpret_cast<const __nv_bfloat16*>(Bl);

    const int t = threadIdx.x, lane = t & 31, wid = t >> 5;
    const int row0 = blockIdx.x * 128;
    if (t < 128) { sB1[t] = b1[t]; sB2[t] = b2[t]; }

    // stage z tile -> Ah/Al (zero-padded past n_nodes)
    {
        const int C4 = K1 / 4;
        for (int idx = t; idx < 128 * C4; idx += 256) {
            int r = idx / C4, c = (idx - r * C4) * 4;
            int gr = row0 + r;
            float4 v = make_float4(0.f, 0.f, 0.f, 0.f);
            if (gr < n_nodes)
                v = *reinterpret_cast<const float4*>(z + (size_t)gr * K1 + c);
            sst2(Ah, Al, r * AS + c,     v.x, v.y);
            sst2(Ah, Al, r * AS + c + 2, v.z, v.w);
        }
    }
    // stage W1^T -> Bh/Bl : B[n][k] = w1[k*HID + n]
    for (int idx = t; idx < K1 * HID; idx += 256) {
        int k = idx >> 7, n = idx & 127;
        sst1(Bh, Bl, n * AS + k, w1[idx]);
    }
    __syncthreads();

    const int m0 = (wid >> 2) * 64;     // {0, 64}
    const int n0 = (wid & 3) * 32;      // {0, 32, 64, 96}

    FragC acc[4][2];

    // ---- GEMM1 ----
    #pragma unroll
    for (int mt = 0; mt < 4; mt++)
        #pragma unroll
        for (int nt = 0; nt < 2; nt++) wmma::fill_fragment(acc[mt][nt], 0.f);
    wmma_gemm<K1 / 16>(acc, fAh, fAl, fBh, fBl, m0, n0);
    __syncthreads();   // all A/B reads done; scratch may overwrite B region

    // ---- epilogue1: T = relu(D1 + b1) -> Ah/Al (via scratch) ----
    #pragma unroll
    for (int mt = 0; mt < 4; mt++)
        #pragma unroll
        for (int nt = 0; nt < 2; nt++)
            wmma::store_matrix_sync(scr + (m0 + mt * 16) * LDS + n0 + nt * 16,
                                    acc[mt][nt], LDS, wmma::mem_row_major);
    __syncwarp();
    #pragma unroll
    for (int rr = 0; rr < 2; rr++) {
        int r = m0 + lane * 2 + rr;                // warp-own 64 rows
        const float* sp = scr + r * LDS + n0;
        #pragma unroll
        for (int c = 0; c < 32; c += 4) {
            float4 v = *reinterpret_cast<const float4*>(sp + c);
            int cc = n0 + c;
            sst2(Ah, Al, r * AS + cc,
                 fmaxf(v.x + sB1[cc], 0.f),     fmaxf(v.y + sB1[cc + 1], 0.f));
            sst2(Ah, Al, r * AS + cc + 2,
                 fmaxf(v.z + sB1[cc + 2], 0.f), fmaxf(v.w + sB1[cc + 3], 0.f));
        }
    }
    __syncthreads();   // scratch reads done; restage W2 over it
    for (int idx = t; idx < HID * HID; idx += 256) {
        int k = idx >> 7, n = idx & 127;
        sst1(Bh, Bl, n * AS + k, w2[idx]);
    }
    __syncthreads();

    // ---- GEMM2 (K = 128) ----
    #pragma unroll
    for (int mt = 0; mt < 4; mt++)
        #pragma unroll
        for (int nt = 0; nt < 2; nt++) wmma::fill_fragment(acc[mt][nt], 0.f);
    wmma_gemm<8>(acc, fAh, fAl, fBh, fBl, m0, n0);
    __syncthreads();   // B reads done; scratch reuse

    // ---- epilogue2: out = relu(D2 + b2) -> gmem ----
    #pragma unroll
    for (int mt = 0; mt < 4; mt++)
        #pragma unroll
        for (int nt = 0; nt < 2; nt++)
            wmma::store_matrix_sync(scr + (m0 + mt * 16) * LDS + n0 + nt * 16,
                                    acc[mt][nt], LDS, wmma::mem_row_major);
    __syncwarp();
    #pragma unroll
    for (int rr = 0; rr < 2; rr++) {
        int r = m0 + lane * 2 + rr;
        int gr = row0 + r;
        if (gr >= n_nodes) continue;
        const float* sp = scr + r * LDS + n0;
        float* op = out + (size_t)gr * HID + n0;
        #pragma unroll
        for (int c = 0; c < 32; c += 4) {
            float4 v = *reinterpret_cast<const float4*>(sp + c);
            int cc = n0 + c;
            float4 o = make_float4(fmaxf(v.x + sB2[cc],     0.f),
                                   fmaxf(v.y + sB2[cc + 1], 0.f),
                                   fmaxf(v.z + sB2[cc + 2], 0.f),
                                   fmaxf(v.w + sB2[cc + 3], 0.f));
            *reinterpret_cast<float4*>(op + c) = o;
        }
    }
}

// ---------------------------------------------------------------------------
// Readout: batch_idx sorted -> run-length accumulate, flush atomics per run.
__global__ void readout_kernel(const float* __restrict__ h,
                               const int* __restrict__ batch, int n_nodes,
                               float* __restrict__ ssum, float* __restrict__ smax,
                               float* __restrict__ cnt) {
    int c = threadIdx.x;          // 128 threads = one column each
    int n0 = blockIdx.x * 128;
    if (n0 >= n_nodes) return;
    int nend = min(n0 + 128, n_nodes);
    int curg = batch[n0];
    float rs = 0.f, rm = 0.f, rc = 0.f;
    for (int n = n0; n < nend; n++) {
        int g = __ldg(batch + n);
        if (g != curg) {
            atomicAdd(&ssum[curg * HID + c], rs);
            atomicMax(reinterpret_cast<int*>(&smax[curg * HID + c]), __float_as_int(rm));
            if (c == 0) atomicAdd(&cnt[curg], rc);
            rs = 0.f; rm = 0.f; rc = 0.f; curg = g;
        }
        float v = h[(size_t)n * HID + c];
        rs += v;
        rm = fmaxf(rm, v);
        rc += 1.f;
    }
    atomicAdd(&ssum[curg * HID + c], rs);
    atomicMax(reinterpret_cast<int*>(&smax[curg * HID + c]), __float_as_int(rm));
    if (c == 0) atomicAdd(&cnt[curg], rc);
}

// ---------------------------------------------------------------------------
__global__ void head_kernel(const float* __restrict__ pool,
                            const float* __restrict__ w1, const float* __restrict__ b1,
                            const float* __restrict__ w2, const float* __restrict__ b2,
                            float* __restrict__ out) {
    __shared__ float repr[2 * HID];
    __shared__ float red[4];
    int g = blockIdx.x;
    int n = threadIdx.x;  // 128
    const float* ssum = pool;
    const float* smax = pool + NG * HID;
    const float* cnt  = pool + 2 * NG * HID;

    float cg = cnt[g];
    float dv = fmaxf(cg, 1.f);
    repr[n]       = ssum[g * HID + n] / dv;
    repr[HID + n] = (cg > 0.f) ? smax[g * HID + n] : 0.f;
    __syncthreads();

    float acc = b1[n];
    #pragma unroll 8
    for (int k = 0; k < 2 * HID; k++) acc += repr[k] * w1[k * HID + n];
    float p = fmaxf(acc, 0.f) * w2[n];

    #pragma unroll
    for (int off = 16; off > 0; off >>= 1) p += __shfl_down_sync(0xffffffffu, p, off);
    if ((n & 31) == 0) red[n >> 5] = p;
    __syncthreads();
    if (n == 0) {
        float logit = red[0] + red[1] + red[2] + red[3] + b2[0];
        out[g] = 1.f / (1.f + expf(-logit));
    }
}

// ---------------------------------------------------------------------------
extern "C" void kernel_launch(void* const* d_in, const int* in_sizes, int n_in,
                              void* d_out, int out_size) {
    const float* x      = (const float*)d_in[0];
    const int*   ei     = (const int*)  d_in[1];
    const int*   batch  = (const int*)  d_in[2];
    const float* g0w1 = (const float*)d_in[3],  *g0b1 = (const float*)d_in[4];
    const float* g0w2 = (const float*)d_in[5],  *g0b2 = (const float*)d_in[6];
    const float* g1w1 = (const float*)d_in[7],  *g1b1 = (const float*)d_in[8];
    const float* g1w2 = (const float*)d_in[9],  *g1b2 = (const float*)d_in[10];
    const float* g2w1 = (const float*)d_in[11], *g2b1 = (const float*)d_in[12];
    const float* g2w2 = (const float*)d_in[13], *g2b2 = (const float*)d_in[14];
    const float* hw1  = (const float*)d_in[15], *hb1  = (const float*)d_in[16];
    const float* hw2  = (const float*)d_in[17], *hb2  = (const float*)d_in[18];
    float* out = (float*)d_out;

    const int N = in_sizes[2];          // 50000 nodes
    const int E = in_sizes[1] / 2;      // 800000 edges
    const int* src = ei;
    const int* dst = ei + E;

    float *agg, *buf0, *buf1, *pool;
    int *deg, *off, *cur, *eidx;
    cudaGetSymbolAddress((void**)&agg,  g_agg);
    cudaGetSymbolAddress((void**)&buf0, g_buf0);
    cudaGetSymbolAddress((void**)&buf1, g_buf1);
    cudaGetSymbolAddress((void**)&pool, g_pool);
    cudaGetSymbolAddress((void**)&deg,  g_deg);
    cudaGetSymbolAddress((void**)&off,  g_off);
    cudaGetSymbolAddress((void**)&cur,  g_cur);
    cudaGetSymbolAddress((void**)&eidx, g_eidx);

    cudaFuncSetAttribute(mma_mlp<64>,  cudaFuncAttributeMaxDynamicSharedMemorySize, MMA_SMEM);
    cudaFuncSetAttribute(mma_mlp<128>, cudaFuncAttributeMaxDynamicSharedMemorySize, MMA_SMEM);

    const int mlp_blocks = (N + 127) / 128;
    const int e_blocks = (E + 255) / 256;
    const int g_blocks = (N + 7) / 8;       // 8 warps/block

    // ---- CSR build (over dst) ----
    zero_i<<<64, 256>>>(deg, N);
    hist_kernel<<<e_blocks, 256>>>(dst, deg, E);
    scan_kernel<<<1, 1024>>>(deg, off, cur, N);
    fill_kernel<<<e_blocks, 256>>>(src, dst, cur, eidx, E);

    // ---- layer 0 (in dim 64) ----
    gather_kernel<64><<<g_blocks, 256>>>(x, off, eidx, agg, N);
    mma_mlp<64><<<mlp_blocks, 256, MMA_SMEM>>>(agg, g0w1, g0b1, g0w2, g0b2, buf0, N);

    // ---- layer 1 ----
    gather_kernel<128><<<g_blocks, 256>>>(buf0, off, eidx, agg, N);
    mma_mlp<128><<<mlp_blocks, 256, MMA_SMEM>>>(agg, g1w1, g1b1, g1w2, g1b2, buf1, N);

    // ---- layer 2 ----
    gather_kernel<128><<<g_blocks, 256>>>(buf1, off, eidx, agg, N);
    mma_mlp<128><<<mlp_blocks, 256, MMA_SMEM>>>(agg, g2w1, g2b1, g2w2, g2b2, buf0, N);

    // ---- readout + head ----
    zero_f<<<256, 256>>>(pool, NG * HID * 2 + NG);
    readout_kernel<<<(N + 127) / 128, 128>>>(buf0, batch, N,
                                             pool, pool + NG * HID, pool + 2 * NG * HID);
    head_kernel<<<NG, 128>>>(pool, hw1, hb1, hw2, hb2, out);
}